// round 1
// baseline (speedup 1.0000x reference)
#include <cuda_runtime.h>
#include <math.h>

#define NH   16
#define DH   64
#define SEQ  2048
#define BATCH 2
#define DM   1024
#define MROWS (BATCH*SEQ)   // 4096

// ---------------- scratch (device globals; no allocations allowed) ----------
__device__ float g_qt[(size_t)BATCH*NH*DH*SEQ];   // [b,h,d,s]
__device__ float g_kt[(size_t)BATCH*NH*DH*SEQ];   // [b,h,d,s]
__device__ float g_v [(size_t)BATCH*NH*SEQ*DH];   // [b,h,s,d]
__device__ float g_o [(size_t)BATCH*SEQ*DM];      // [b,s,h*dh]
__device__ float g_bias[NH*4096];                 // [h][rel+2047], rel = k - q

// ---------------- relative-position bias table ------------------------------
// Bit-matches the JAX reference: XLA:GPU lowers jnp.log to libdevice __nv_logf
// (== CUDA logf); divisor np.log(16.0) becomes a float32 constant.
__global__ void bias_kernel(const float* __restrict__ rel_emb) {
    int idx = blockIdx.x * blockDim.x + threadIdx.x;   // 0..4094
    if (idx >= 4095) return;
    int rel = idx - 2047;                 // rel = pos_k - pos_q
    int bucket = (rel > 0) ? 16 : 0;
    int r = abs(rel);
    int bval;
    if (r < 8) {
        bval = r;
    } else {
        float v = logf((float)r / 8.0f) / 2.772588722239781f * 8.0f;
        int vi = (int)v;                  // truncation, matches astype(int32)
        bval = min(8 + vi, 15);
    }
    bucket += bval;
#pragma unroll
    for (int h = 0; h < NH; h++)
        g_bias[h*4096 + idx] = rel_emb[bucket*NH + h];
}

// ---------------- tiled SGEMM: C = A[M,K] @ B[K,N] --------------------------
// cmode: 0 -> g_qt ([b,h,d,s]), 1 -> g_kt, 2 -> g_v ([b,h,s,d]), 3 -> Cext row-major
// amode: 0 -> Aext, 1 -> g_o
#define BM 128
#define BN 128
#define BKK 8
__global__ __launch_bounds__(256) void sgemm_kernel(
    const float* __restrict__ Aext, const float* __restrict__ Bw,
    float* __restrict__ Cext, int M, int N, int K, int amode, int cmode)
{
    __shared__ __align__(16) float As[BKK][BM];
    __shared__ __align__(16) float Bs[BKK][BN];
    const float* A = amode ? g_o : Aext;

    int tid = threadIdx.x;
    int bx = blockIdx.x, by = blockIdx.y;
    int arow = tid >> 1;            // 0..127
    int acol = (tid & 1) * 4;       // 0 or 4
    int brow = tid >> 5;            // 0..7
    int bcol = (tid & 31) * 4;      // 0..124
    int tx = tid & 15, ty = tid >> 4;

    float acc[8][8];
#pragma unroll
    for (int i = 0; i < 8; i++)
#pragma unroll
        for (int j = 0; j < 8; j++) acc[i][j] = 0.f;

    const float* Ap = A + (size_t)(by*BM)*K;
    const float* Bp = Bw + bx*BN;

    for (int k0 = 0; k0 < K; k0 += BKK) {
        float4 av = *(const float4*)(Ap + (size_t)arow*K + k0 + acol);
        As[acol+0][arow] = av.x; As[acol+1][arow] = av.y;
        As[acol+2][arow] = av.z; As[acol+3][arow] = av.w;
        *(float4*)&Bs[brow][bcol] = *(const float4*)(Bp + (size_t)(k0+brow)*N + bcol);
        __syncthreads();
#pragma unroll
        for (int k = 0; k < BKK; k++) {
            float ar[8], br[8];
#pragma unroll
            for (int i = 0; i < 8; i++) ar[i] = As[k][ty*8 + i];
#pragma unroll
            for (int j = 0; j < 8; j++) br[j] = Bs[k][tx*8 + j];
#pragma unroll
            for (int i = 0; i < 8; i++)
#pragma unroll
                for (int j = 0; j < 8; j++) acc[i][j] += ar[i]*br[j];
        }
        __syncthreads();
    }

    int mbase = by*BM + ty*8;
    int nbase = bx*BN + tx*8;
    if (cmode == 3) {
#pragma unroll
        for (int i = 0; i < 8; i++) {
            float* c = Cext + (size_t)(mbase+i)*N + nbase;
            *(float4*)c       = make_float4(acc[i][0],acc[i][1],acc[i][2],acc[i][3]);
            *(float4*)(c + 4) = make_float4(acc[i][4],acc[i][5],acc[i][6],acc[i][7]);
        }
    } else if (cmode == 2) {
        int h  = nbase >> 6;
        int d0 = nbase & 63;
#pragma unroll
        for (int i = 0; i < 8; i++) {
            int m = mbase + i;
            int b = m >> 11, s = m & 2047;
            float* c = g_v + (((size_t)(b*NH + h)*SEQ + s)*DH + d0);
            *(float4*)c       = make_float4(acc[i][0],acc[i][1],acc[i][2],acc[i][3]);
            *(float4*)(c + 4) = make_float4(acc[i][4],acc[i][5],acc[i][6],acc[i][7]);
        }
    } else {
        float* dst = (cmode == 0) ? g_qt : g_kt;
        int h  = nbase >> 6;
        int d0 = nbase & 63;
#pragma unroll
        for (int i = 0; i < 8; i++) {
            int m = mbase + i;
            int b = m >> 11, s = m & 2047;
#pragma unroll
            for (int j = 0; j < 8; j++)
                dst[((size_t)(b*NH + h)*DH + d0 + j)*SEQ + s] = acc[i][j];
        }
    }
}

// ---------------- flash attention (fp32, online softmax) --------------------
// grid: (SEQ/64, B*H), block: 128 threads (tx 0..15 -> 4 key cols / 4 out dims,
// ty 0..7 -> 8 query rows).
__global__ __launch_bounds__(128) void attn_kernel() {
    __shared__ __align__(16) float qs [DH*64];   // [d][s_q]  16KB
    __shared__ __align__(16) float kps[DH*64];   // K [d][s_k]  OR  P [m][j]
    __shared__ __align__(16) float vs [64*DH];   // [s_k][d]  16KB

    int bh = blockIdx.y;
    int h  = bh & (NH-1);
    int b  = bh >> 4;
    int q0 = blockIdx.x * 64;
    int tid = threadIdx.x;
    int tx = tid & 15, ty = tid >> 4;

    const float* qg = g_qt + (size_t)bh * DH * SEQ;
    const float* kg = g_kt + (size_t)bh * DH * SEQ;
    const float* vg = g_v  + (size_t)bh * SEQ * DH;
    const float* biasrow = g_bias + h*4096;

    // load Q tile: qs[d][s] = qg[d*SEQ + q0 + s]
    for (int e = tid; e < DH*16; e += 128) {
        int d = e >> 4, s4 = e & 15;
        ((float4*)qs)[d*16 + s4] = ((const float4*)(qg + (size_t)d*SEQ + q0))[s4];
    }

    float acc[8][4], mrow[8], lrow[8];
#pragma unroll
    for (int i = 0; i < 8; i++) {
        mrow[i] = -1e30f; lrow[i] = 0.f;
#pragma unroll
        for (int j = 0; j < 4; j++) acc[i][j] = 0.f;
    }
    __syncthreads();

    for (int k0 = 0; k0 < SEQ; k0 += 64) {
        // load K tile (d-major) and V tile (s-major)
        for (int e = tid; e < DH*16; e += 128) {
            int d = e >> 4, s4 = e & 15;
            ((float4*)kps)[e] = ((const float4*)(kg + (size_t)d*SEQ + k0))[s4];
            ((float4*)vs )[e] = ((const float4*)(vg + (size_t)k0*DH))[e];
        }
        __syncthreads();

        // S = Q K^T  (64x64 tile; per-thread 8x4)
        float sc[8][4];
#pragma unroll
        for (int i = 0; i < 8; i++)
#pragma unroll
            for (int j = 0; j < 4; j++) sc[i][j] = 0.f;

        for (int d = 0; d < DH; d++) {
            float4 a0 = ((float4*)qs )[d*16 + 2*ty];
            float4 a1 = ((float4*)qs )[d*16 + 2*ty + 1];
            float4 bv = ((float4*)kps)[d*16 + tx];
            float a[8] = {a0.x,a0.y,a0.z,a0.w,a1.x,a1.y,a1.z,a1.w};
            float bb[4] = {bv.x,bv.y,bv.z,bv.w};
#pragma unroll
            for (int i = 0; i < 8; i++)
#pragma unroll
                for (int j = 0; j < 4; j++) sc[i][j] += a[i]*bb[j];
        }

        // bias: rel = (k0+4tx+j) - (q0+8ty+i); 11 distinct values per thread
        int relbase = k0 + 4*tx - (q0 + 8*ty) + 2047;
        float bvals[11];
#pragma unroll
        for (int t = 0; t < 11; t++) bvals[t] = biasrow[relbase - 7 + t];
#pragma unroll
        for (int i = 0; i < 8; i++)
#pragma unroll
            for (int j = 0; j < 4; j++) sc[i][j] += bvals[j - i + 7];

        __syncthreads();   // finished reading kps as K

        // online softmax; write P into kps (reused as [m][j])
#pragma unroll
        for (int i = 0; i < 8; i++) {
            float tm = fmaxf(fmaxf(sc[i][0], sc[i][1]), fmaxf(sc[i][2], sc[i][3]));
#pragma unroll
            for (int o = 8; o >= 1; o >>= 1)
                tm = fmaxf(tm, __shfl_xor_sync(0xffffffffu, tm, o));
            float mnew = fmaxf(mrow[i], tm);
            float corr = __expf(mrow[i] - mnew);
            mrow[i] = mnew;
            float p0 = __expf(sc[i][0] - mnew);
            float p1 = __expf(sc[i][1] - mnew);
            float p2 = __expf(sc[i][2] - mnew);
            float p3 = __expf(sc[i][3] - mnew);
            float psum = p0 + p1 + p2 + p3;
#pragma unroll
            for (int o = 8; o >= 1; o >>= 1)
                psum += __shfl_xor_sync(0xffffffffu, psum, o);
            lrow[i] = lrow[i]*corr + psum;
#pragma unroll
            for (int j = 0; j < 4; j++) acc[i][j] *= corr;
            ((float4*)kps)[(8*ty + i)*16 + tx] = make_float4(p0, p1, p2, p3);
        }
        __syncthreads();

        // O += P V   (per-thread 8 rows x 4 dims)
        for (int j = 0; j < 64; j++) {
            float4 bv = ((float4*)vs)[j*16 + tx];
#pragma unroll
            for (int i = 0; i < 8; i++) {
                float a = kps[(8*ty + i)*64 + j];
                acc[i][0] += a*bv.x; acc[i][1] += a*bv.y;
                acc[i][2] += a*bv.z; acc[i][3] += a*bv.w;
            }
        }
        __syncthreads();   // protect kps/vs before next tile load
    }

    // normalize + store to g_o [b,s,h*64+d]
#pragma unroll
    for (int i = 0; i < 8; i++) {
        float inv = 1.0f / lrow[i];
        int m = q0 + 8*ty + i;
        float4 o4 = make_float4(acc[i][0]*inv, acc[i][1]*inv,
                                acc[i][2]*inv, acc[i][3]*inv);
        ((float4*)(g_o + ((size_t)b*SEQ + m)*DM + h*DH))[tx] = o4;
    }
}

// ---------------- launch -----------------------------------------------------
extern "C" void kernel_launch(void* const* d_in, const int* in_sizes, int n_in,
                              void* d_out, int out_size) {
    const float* X   = (const float*)d_in[0];
    const float* Wq  = (const float*)d_in[1];
    const float* Wk  = (const float*)d_in[2];
    const float* Wv  = (const float*)d_in[3];
    const float* Wo  = (const float*)d_in[4];
    const float* rel = (const float*)d_in[5];
    float* out = (float*)d_out;

    bias_kernel<<<16, 256>>>(rel);

    dim3 gg(DM/BN, MROWS/BM);   // (8, 32)
    sgemm_kernel<<<gg, 256>>>(X, Wq, nullptr, MROWS, DM, DM, 0, 0);
    sgemm_kernel<<<gg, 256>>>(X, Wk, nullptr, MROWS, DM, DM, 0, 1);
    sgemm_kernel<<<gg, 256>>>(X, Wv, nullptr, MROWS, DM, DM, 0, 2);

    attn_kernel<<<dim3(SEQ/64, BATCH*NH), 128>>>();

    sgemm_kernel<<<gg, 256>>>(nullptr, Wo, out, MROWS, DM, DM, 1, 3);
}

// round 3
// speedup vs baseline: 1.2222x; 1.2222x over previous
#include <cuda_runtime.h>
#include <math.h>

#define NH   16
#define DH   64
#define SEQ  2048
#define BATCH 2
#define DM   1024
#define MROWS (BATCH*SEQ)   // 4096

typedef unsigned long long u64;

// ---- packed f32x2 helpers (FFMA2: 2x fp32 throughput, per-lane identical math)
__device__ __forceinline__ u64 pk2(float x, float y) {
    u64 r; asm("mov.b64 %0, {%1, %2};" : "=l"(r) : "f"(x), "f"(y)); return r;
}
__device__ __forceinline__ void fma2(u64 &acc, u64 a, u64 b) {
    asm("fma.rn.f32x2 %0, %1, %2, %0;" : "+l"(acc) : "l"(a), "l"(b));
}
__device__ __forceinline__ void mul2(u64 &acc, u64 a) {
    asm("mul.rn.f32x2 %0, %0, %1;" : "+l"(acc) : "l"(a));
}
__device__ __forceinline__ float lo2(u64 v){ return __uint_as_float((unsigned)v); }
__device__ __forceinline__ float hi2(u64 v){ return __uint_as_float((unsigned)(v>>32)); }

// ---------------- scratch (device globals; no allocations allowed) ----------
__device__ float g_qt[(size_t)BATCH*NH*DH*SEQ];   // [b,h,d,s]
__device__ float g_kt[(size_t)BATCH*NH*DH*SEQ];   // [b,h,d,s]
__device__ float g_v [(size_t)BATCH*NH*SEQ*DH];   // [b,h,s,d]
__device__ float g_o [(size_t)BATCH*SEQ*DM];      // [b,s,h*dh]
__device__ float g_bias[NH*4096];                 // [h][rel+2047], rel = k - q

// ---------------- relative-position bias table ------------------------------
__global__ void bias_kernel(const float* __restrict__ rel_emb) {
    int idx = blockIdx.x * blockDim.x + threadIdx.x;   // 0..4094
    if (idx >= 4095) return;
    int rel = idx - 2047;                 // rel = pos_k - pos_q
    int bucket = (rel > 0) ? 16 : 0;
    int r = abs(rel);
    int bval;
    if (r < 8) {
        bval = r;
    } else {
        float v = logf((float)r / 8.0f) / 2.772588722239781f * 8.0f;
        int vi = (int)v;                  // truncation, matches astype(int32)
        bval = min(8 + vi, 15);
    }
    bucket += bval;
#pragma unroll
    for (int h = 0; h < NH; h++)
        g_bias[h*4096 + idx] = rel_emb[bucket*NH + h];
}

// ---------------- tiled SGEMM: C = A[M,K] @ B[K,N] --------------------------
// cmode: 0 -> g_qt ([b,h,d,s]), 1 -> g_kt, 2 -> g_v ([b,h,s,d]), 3 -> Cext row-major
// amode: 0 -> Aext, 1 -> g_o
#define BKK 8
#define ROWW 164   // 128 data floats + skew headroom (SKW(127)=163)
__device__ __forceinline__ int SKW(int m){ return m + 12*(m>>5); }

__global__ __launch_bounds__(256) void sgemm_kernel(
    const float* __restrict__ Aext, const float* __restrict__ Bw,
    float* __restrict__ Cext, int M, int N, int K, int amode, int cmode)
{
    __shared__ __align__(16) float As[2][BKK][ROWW];
    __shared__ __align__(16) float Bs[2][BKK][ROWW];
    const float* A = amode ? g_o : Aext;

    int tid = threadIdx.x;
    int bx = blockIdx.x, by = blockIdx.y;
    int arow = tid >> 1;            // 0..127
    int acol = (tid & 1) * 4;       // 0 or 4
    int brow = tid >> 5;            // 0..7
    int bcol = (tid & 31) * 4;      // 0..124
    int tx = tid & 15, ty = tid >> 4;
    int wa = SKW(arow), wb = SKW(bcol);
    int w8ty = SKW(ty*8), w8tx = SKW(tx*8);

    u64 acc2[4][8];
#pragma unroll
    for (int ip = 0; ip < 4; ip++)
#pragma unroll
        for (int j = 0; j < 8; j++) acc2[ip][j] = 0ull;

    const float* Ap = A  + (size_t)(by*128 + arow)*K + acol;
    const float* Bp = Bw + (size_t)brow*N + bx*128 + bcol;

    // prologue: fill buffer 0
    float4 av = *(const float4*)Ap;
    float4 bv = *(const float4*)Bp;
    As[0][acol+0][wa]=av.x; As[0][acol+1][wa]=av.y;
    As[0][acol+2][wa]=av.z; As[0][acol+3][wa]=av.w;
    *(float4*)&Bs[0][brow][wb] = bv;
    __syncthreads();

    const int NT = 1024/BKK;  // K == 1024 always here
    for (int kt = 0; kt < NT; kt++) {
        int buf = kt & 1;
        if (kt + 1 < NT) {
            av = *(const float4*)(Ap + (kt+1)*BKK);
            bv = *(const float4*)(Bp + (size_t)(kt+1)*BKK*N);
        }
#pragma unroll
        for (int k = 0; k < BKK; k++) {
            const float* ar = &As[buf][k][w8ty];
            const float* br = &Bs[buf][k][w8tx];
            ulonglong2 a01 = *(const ulonglong2*)ar;
            ulonglong2 a23 = *(const ulonglong2*)(ar+4);
            float4 b0 = *(const float4*)br;
            float4 b1 = *(const float4*)(br+4);
            u64 ap[4] = {a01.x, a01.y, a23.x, a23.y};
            u64 bd[8] = {pk2(b0.x,b0.x), pk2(b0.y,b0.y), pk2(b0.z,b0.z), pk2(b0.w,b0.w),
                         pk2(b1.x,b1.x), pk2(b1.y,b1.y), pk2(b1.z,b1.z), pk2(b1.w,b1.w)};
#pragma unroll
            for (int ip = 0; ip < 4; ip++)
#pragma unroll
                for (int j = 0; j < 8; j++) fma2(acc2[ip][j], ap[ip], bd[j]);
        }
        if (kt + 1 < NT) {
            int nb = buf ^ 1;
            As[nb][acol+0][wa]=av.x; As[nb][acol+1][wa]=av.y;
            As[nb][acol+2][wa]=av.z; As[nb][acol+3][wa]=av.w;
            *(float4*)&Bs[nb][brow][wb] = bv;
            __syncthreads();
        }
    }

    float acc[8][8];
#pragma unroll
    for (int ip = 0; ip < 4; ip++)
#pragma unroll
        for (int j = 0; j < 8; j++) {
            acc[2*ip  ][j] = lo2(acc2[ip][j]);
            acc[2*ip+1][j] = hi2(acc2[ip][j]);
        }

    int mbase = by*128 + ty*8;
    int nbase = bx*128 + tx*8;
    if (cmode == 3) {
#pragma unroll
        for (int i = 0; i < 8; i++) {
            float* c = Cext + (size_t)(mbase+i)*N + nbase;
            *(float4*)c       = make_float4(acc[i][0],acc[i][1],acc[i][2],acc[i][3]);
            *(float4*)(c + 4) = make_float4(acc[i][4],acc[i][5],acc[i][6],acc[i][7]);
        }
    } else if (cmode == 2) {
        int h  = nbase >> 6;
        int d0 = nbase & 63;
#pragma unroll
        for (int i = 0; i < 8; i++) {
            int m = mbase + i;
            int b = m >> 11, s = m & 2047;
            float* c = g_v + (((size_t)(b*NH + h)*SEQ + s)*DH + d0);
            *(float4*)c       = make_float4(acc[i][0],acc[i][1],acc[i][2],acc[i][3]);
            *(float4*)(c + 4) = make_float4(acc[i][4],acc[i][5],acc[i][6],acc[i][7]);
        }
    } else {
        float* dst = (cmode == 0) ? g_qt : g_kt;
        int h  = nbase >> 6;
        int d0 = nbase & 63;
        int b = mbase >> 11, s = mbase & 2047;   // 128-block never crosses batch
        float* base = dst + ((size_t)(b*NH + h)*DH + d0)*SEQ + s;
#pragma unroll
        for (int j = 0; j < 8; j++) {
            *(float4*)(base + (size_t)j*SEQ)     =
                make_float4(acc[0][j],acc[1][j],acc[2][j],acc[3][j]);
            *(float4*)(base + (size_t)j*SEQ + 4) =
                make_float4(acc[4][j],acc[5][j],acc[6][j],acc[7][j]);
        }
    }
}

// ---------------- flash attention (fp32, online softmax, f32x2) -------------
// grid: (SEQ/64, B*H), block 128 (tx 0..15 -> 4 key cols / 4 out dims,
// ty 0..7 -> 8 query rows).
__global__ __launch_bounds__(128) void attn_kernel() {
    __shared__ __align__(16) float qs [DH*64];   // Q [d][s]           16KB
    __shared__ __align__(16) float kps[DH*64];   // K [d][s] / P swz   16KB
    __shared__ __align__(16) float vs [64*DH];   // V [s_k][d]         16KB

    int bh = blockIdx.y;
    int h  = bh & (NH-1);
    int b  = bh >> 4;
    int q0 = blockIdx.x * 64;
    int tid = threadIdx.x;
    int tx = tid & 15, ty = tid >> 4;

    const float* qg = g_qt + (size_t)bh * DH * SEQ;
    const float* kg = g_kt + (size_t)bh * DH * SEQ;
    const float* vg = g_v  + (size_t)bh * SEQ * DH;
    const float* biasrow = g_bias + h*4096;

    for (int e = tid; e < DH*16; e += 128) {
        int d = e >> 4, s4 = e & 15;
        ((float4*)qs)[d*16 + s4] = ((const float4*)(qg + (size_t)d*SEQ + q0))[s4];
    }

    u64 accP2[8][2];
    float mrow[8], lrow[8];
#pragma unroll
    for (int i = 0; i < 8; i++) {
        mrow[i] = -1e30f; lrow[i] = 0.f;
        accP2[i][0] = 0ull; accP2[i][1] = 0ull;
    }
    __syncthreads();

    for (int k0 = 0; k0 < SEQ; k0 += 64) {
        for (int e = tid; e < DH*16; e += 128) {
            int d = e >> 4, s4 = e & 15;
            ((float4*)kps)[e] = ((const float4*)(kg + (size_t)d*SEQ + k0))[s4];
            ((float4*)vs )[e] = ((const float4*)(vg + (size_t)k0*DH))[e];
        }
        __syncthreads();

        // ---- S = Q K^T : packed along i (q-pairs natural), k duplicated
        u64 sc2[4][4];
#pragma unroll
        for (int ip = 0; ip < 4; ip++)
#pragma unroll
            for (int j = 0; j < 4; j++) sc2[ip][j] = 0ull;

#pragma unroll 4
        for (int d = 0; d < DH; d++) {
            const float* qp = qs + d*64 + 8*ty;
            ulonglong2 qa = *(const ulonglong2*)qp;
            ulonglong2 qb = *(const ulonglong2*)(qp + 4);
            u64 ap[4] = {qa.x, qa.y, qb.x, qb.y};
            float4 kf = ((const float4*)kps)[d*16 + tx];
            u64 kd[4] = {pk2(kf.x,kf.x), pk2(kf.y,kf.y), pk2(kf.z,kf.z), pk2(kf.w,kf.w)};
#pragma unroll
            for (int ip = 0; ip < 4; ip++)
#pragma unroll
                for (int j = 0; j < 4; j++) fma2(sc2[ip][j], ap[ip], kd[j]);
        }

        float sc[8][4];
#pragma unroll
        for (int ip = 0; ip < 4; ip++)
#pragma unroll
            for (int j = 0; j < 4; j++) {
                sc[2*ip  ][j] = lo2(sc2[ip][j]);
                sc[2*ip+1][j] = hi2(sc2[ip][j]);
            }

        // bias: rel = (k0+4tx+j) - (q0+8ty+i)
        int relbase = k0 + 4*tx - (q0 + 8*ty) + 2047;
        float bvals[11];
#pragma unroll
        for (int t = 0; t < 11; t++) bvals[t] = biasrow[relbase - 7 + t];
#pragma unroll
        for (int i = 0; i < 8; i++)
#pragma unroll
            for (int j = 0; j < 4; j++) sc[i][j] += bvals[j - i + 7];

        __syncthreads();   // finished reading kps as K

        // ---- online softmax; P written swizzled (block ^ ty) into kps
#pragma unroll
        for (int i = 0; i < 8; i++) {
            float tm = fmaxf(fmaxf(sc[i][0], sc[i][1]), fmaxf(sc[i][2], sc[i][3]));
#pragma unroll
            for (int o = 8; o >= 1; o >>= 1)
                tm = fmaxf(tm, __shfl_xor_sync(0xffffffffu, tm, o));
            float mnew = fmaxf(mrow[i], tm);
            float corr = __expf(mrow[i] - mnew);
            mrow[i] = mnew;
            float p0 = __expf(sc[i][0] - mnew);
            float p1 = __expf(sc[i][1] - mnew);
            float p2 = __expf(sc[i][2] - mnew);
            float p3 = __expf(sc[i][3] - mnew);
            float psum = p0 + p1 + p2 + p3;
#pragma unroll
            for (int o = 8; o >= 1; o >>= 1)
                psum += __shfl_xor_sync(0xffffffffu, psum, o);
            lrow[i] = lrow[i]*corr + psum;
            u64 cd = pk2(corr, corr);
            mul2(accP2[i][0], cd);
            mul2(accP2[i][1], cd);
            ((float4*)kps)[(8*ty + i)*16 + (tx ^ ty)] = make_float4(p0, p1, p2, p3);
        }
        __syncthreads();

        // ---- O += P V : packed along d (v-pairs natural), p duplicated
#pragma unroll 2
        for (int jj = 0; jj < 16; jj++) {
            int j0 = jj*4;
            ulonglong2 v0 = ((const ulonglong2*)vs)[(j0+0)*16 + tx];
            ulonglong2 v1 = ((const ulonglong2*)vs)[(j0+1)*16 + tx];
            ulonglong2 v2 = ((const ulonglong2*)vs)[(j0+2)*16 + tx];
            ulonglong2 v3 = ((const ulonglong2*)vs)[(j0+3)*16 + tx];
#pragma unroll
            for (int i = 0; i < 8; i++) {
                float4 pf = ((const float4*)kps)[(8*ty + i)*16 + (jj ^ ty)];
                u64 pd0 = pk2(pf.x, pf.x), pd1 = pk2(pf.y, pf.y);
                u64 pd2 = pk2(pf.z, pf.z), pd3 = pk2(pf.w, pf.w);
                fma2(accP2[i][0], pd0, v0.x); fma2(accP2[i][1], pd0, v0.y);
                fma2(accP2[i][0], pd1, v1.x); fma2(accP2[i][1], pd1, v1.y);
                fma2(accP2[i][0], pd2, v2.x); fma2(accP2[i][1], pd2, v2.y);
                fma2(accP2[i][0], pd3, v3.x); fma2(accP2[i][1], pd3, v3.y);
            }
        }
        __syncthreads();   // protect kps/vs before next tile load
    }

    // normalize + store to g_o [b,s,h*64+d]
#pragma unroll
    for (int i = 0; i < 8; i++) {
        float inv = 1.0f / lrow[i];
        int m = q0 + 8*ty + i;
        float4 o4 = make_float4(lo2(accP2[i][0])*inv, hi2(accP2[i][0])*inv,
                                lo2(accP2[i][1])*inv, hi2(accP2[i][1])*inv);
        ((float4*)(g_o + ((size_t)b*SEQ + m)*DM + h*DH))[tx] = o4;
    }
}

// ---------------- launch -----------------------------------------------------
extern "C" void kernel_launch(void* const* d_in, const int* in_sizes, int n_in,
                              void* d_out, int out_size) {
    const float* X   = (const float*)d_in[0];
    const float* Wq  = (const float*)d_in[1];
    const float* Wk  = (const float*)d_in[2];
    const float* Wv  = (const float*)d_in[3];
    const float* Wo  = (const float*)d_in[4];
    const float* rel = (const float*)d_in[5];
    float* out = (float*)d_out;

    bias_kernel<<<16, 256>>>(rel);

    dim3 gg(DM/128, MROWS/128);   // (8, 32)
    sgemm_kernel<<<gg, 256>>>(X, Wq, nullptr, MROWS, DM, DM, 0, 0);
    sgemm_kernel<<<gg, 256>>>(X, Wk, nullptr, MROWS, DM, DM, 0, 1);
    sgemm_kernel<<<gg, 256>>>(X, Wv, nullptr, MROWS, DM, DM, 0, 2);

    attn_kernel<<<dim3(SEQ/64, BATCH*NH), 128>>>();

    sgemm_kernel<<<gg, 256>>>(nullptr, Wo, out, MROWS, DM, DM, 1, 3);
}

// round 5
// speedup vs baseline: 1.5800x; 1.2928x over previous
#include <cuda_runtime.h>
#include <cuda_bf16.h>
#include <math.h>
#include <stdint.h>

#define NH   16
#define DH   64
#define SEQ  2048
#define BATCH 2
#define DM   1024
#define MROWS (BATCH*SEQ)   // 4096

typedef unsigned long long u64;

// ---- packed f32x2 helpers (attention kernel) -------------------------------
__device__ __forceinline__ u64 pk2(float x, float y) {
    u64 r; asm("mov.b64 %0, {%1, %2};" : "=l"(r) : "f"(x), "f"(y)); return r;
}
__device__ __forceinline__ void fma2(u64 &acc, u64 a, u64 b) {
    asm("fma.rn.f32x2 %0, %1, %2, %0;" : "+l"(acc) : "l"(a), "l"(b));
}
__device__ __forceinline__ void mul2(u64 &acc, u64 a) {
    asm("mul.rn.f32x2 %0, %0, %1;" : "+l"(acc) : "l"(a));
}
__device__ __forceinline__ float lo2(u64 v){ return __uint_as_float((unsigned)v); }
__device__ __forceinline__ float hi2(u64 v){ return __uint_as_float((unsigned)(v>>32)); }

__device__ __forceinline__ uint32_t smem_u32(const void* p) {
    uint32_t a;
    asm("{ .reg .u64 t; cvta.to.shared.u64 t, %1; cvt.u32.u64 %0, t; }"
        : "=r"(a) : "l"(p));
    return a;
}
__device__ __forceinline__ void cpa16(uint32_t s, const void* g) {
    asm volatile("cp.async.cg.shared.global [%0], [%1], 16;" :: "r"(s), "l"(g));
}
__device__ __forceinline__ void ldsm4(uint32_t r[4], uint32_t a) {
    asm volatile("ldmatrix.sync.aligned.m8n8.x4.shared.b16 {%0,%1,%2,%3}, [%4];"
                 : "=r"(r[0]), "=r"(r[1]), "=r"(r[2]), "=r"(r[3]) : "r"(a));
}
__device__ __forceinline__ void mma16816(float c[4], const uint32_t a[4],
                                         const uint32_t b0, const uint32_t b1) {
    asm volatile("mma.sync.aligned.m16n8k16.row.col.f32.bf16.bf16.f32 "
        "{%0,%1,%2,%3}, {%4,%5,%6,%7}, {%8,%9}, {%0,%1,%2,%3};"
        : "+f"(c[0]), "+f"(c[1]), "+f"(c[2]), "+f"(c[3])
        : "r"(a[0]), "r"(a[1]), "r"(a[2]), "r"(a[3]), "r"(b0), "r"(b1));
}

// ---------------- scratch (device globals; no allocations allowed) ----------
__device__ float g_qt[(size_t)BATCH*NH*DH*SEQ];   // [b,h,d,s]
__device__ float g_kt[(size_t)BATCH*NH*DH*SEQ];   // [b,h,d,s]
__device__ float g_v [(size_t)BATCH*NH*SEQ*DH];   // [b,h,s,d]
__device__ float g_o [(size_t)BATCH*SEQ*DM];      // [b,s,h*dh]
__device__ float g_bias[NH*4096];                 // [h][rel+2047]
__device__ __nv_bfloat16 g_xh[(size_t)MROWS*DM];  // X hi
__device__ __nv_bfloat16 g_xl[(size_t)MROWS*DM];  // X lo
__device__ __nv_bfloat16 g_oh[(size_t)MROWS*DM];  // attn-out hi
__device__ __nv_bfloat16 g_ol[(size_t)MROWS*DM];  // attn-out lo
__device__ __nv_bfloat16 g_wth[4*(size_t)DM*DM];  // W^T hi  [w][n][k]
__device__ __nv_bfloat16 g_wtl[4*(size_t)DM*DM];  // W^T lo

// ---------------- relative-position bias table ------------------------------
__global__ void bias_kernel(const float* __restrict__ rel_emb) {
    int idx = blockIdx.x * blockDim.x + threadIdx.x;   // 0..4094
    if (idx >= 4095) return;
    int rel = idx - 2047;
    int bucket = (rel > 0) ? 16 : 0;
    int r = abs(rel);
    int bval;
    if (r < 8) bval = r;
    else {
        float v = logf((float)r / 8.0f) / 2.772588722239781f * 8.0f;
        bval = min(8 + (int)v, 15);
    }
    bucket += bval;
#pragma unroll
    for (int h = 0; h < NH; h++)
        g_bias[h*4096 + idx] = rel_emb[bucket*NH + h];
}

// ---------------- fp32 -> bf16 hi/lo split (X or attention output) ----------
__global__ void conv_split(const float4* __restrict__ src_ext, int mode) {
    int i = blockIdx.x * blockDim.x + threadIdx.x;    // n4 = 1048576
    const float4* src = mode ? (const float4*)g_o : src_ext;
    __nv_bfloat16* H = mode ? g_oh : g_xh;
    __nv_bfloat16* L = mode ? g_ol : g_xl;
    float4 v = src[i];
    __nv_bfloat16 h0 = __float2bfloat16(v.x), h1 = __float2bfloat16(v.y);
    __nv_bfloat16 h2 = __float2bfloat16(v.z), h3 = __float2bfloat16(v.w);
    __nv_bfloat16 l0 = __float2bfloat16(v.x - __bfloat162float(h0));
    __nv_bfloat16 l1 = __float2bfloat16(v.y - __bfloat162float(h1));
    __nv_bfloat16 l2 = __float2bfloat16(v.z - __bfloat162float(h2));
    __nv_bfloat16 l3 = __float2bfloat16(v.w - __bfloat162float(h3));
    ((__nv_bfloat162*)H)[2*i]   = __halves2bfloat162(h0, h1);
    ((__nv_bfloat162*)H)[2*i+1] = __halves2bfloat162(h2, h3);
    ((__nv_bfloat162*)L)[2*i]   = __halves2bfloat162(l0, l1);
    ((__nv_bfloat162*)L)[2*i+1] = __halves2bfloat162(l2, l3);
}

// ---------------- weight transpose + split: W[K][N] -> W^T[N][K] bf16 -------
__global__ void conv_wT(const float* __restrict__ W0, const float* __restrict__ W1,
                        const float* __restrict__ W2, const float* __restrict__ W3) {
    __shared__ float t[32][33];
    int z = blockIdx.z;
    const float* W = (z == 0) ? W0 : (z == 1) ? W1 : (z == 2) ? W2 : W3;
    __nv_bfloat16* oh = g_wth + (size_t)z*DM*DM;
    __nv_bfloat16* ol = g_wtl + (size_t)z*DM*DM;
    int k0 = blockIdx.y*32, n0 = blockIdx.x*32;
    int tx = threadIdx.x, ty = threadIdx.y;   // (32, 8)
#pragma unroll
    for (int j = 0; j < 4; j++)
        t[tx][ty + 8*j] = W[(size_t)(k0 + ty + 8*j)*DM + n0 + tx];
    __syncthreads();
#pragma unroll
    for (int j = 0; j < 4; j++) {
        float v = t[ty + 8*j][tx];
        __nv_bfloat16 h = __float2bfloat16(v);
        __nv_bfloat16 l = __float2bfloat16(v - __bfloat162float(h));
        size_t o = (size_t)(n0 + ty + 8*j)*DM + k0 + tx;
        oh[o] = h; ol[o] = l;
    }
}

// ---------------- warp-MMA GEMM (HMMA bf16, 3-pass hi/lo) -------------------
// C[4096,1024] = A @ W.  CTA tile 128x128, 8 warps of 64x32, K chunk 32.
// cmode: 0 -> g_qt [b,h,d,s], 1 -> g_kt, 2 -> g_v [b,h,s,d], 3 -> Cext row-major
#define ST_BYTES 40960          // 4 arrays x 128 rows x 80B
#define OFF_AH 0
#define OFF_AL 10240
#define OFF_BH 20480
#define OFF_BL 30720
#define G_SMEM (2*ST_BYTES)     // 81920; also >= 128*136*4 epilogue floats

__global__ __launch_bounds__(256) void gemm_mma(int asel, int wsel,
                                                float* __restrict__ Cext, int cmode) {
    extern __shared__ __align__(16) char sm[];
    uint32_t sb = smem_u32(sm);
    const int tid = threadIdx.x, lane = tid & 31, w = tid >> 5;
    const int wm = w >> 2, wn = w & 3;
    const int bx = blockIdx.x, by = blockIdx.y;

    const __nv_bfloat16* Ah = (asel ? g_oh : g_xh) + (size_t)(by*128)*DM;
    const __nv_bfloat16* Al = (asel ? g_ol : g_xl) + (size_t)(by*128)*DM;
    const __nv_bfloat16* Bh = g_wth + (size_t)wsel*DM*DM + (size_t)(bx*128)*DM;
    const __nv_bfloat16* Bl = g_wtl + (size_t)wsel*DM*DM + (size_t)(bx*128)*DM;

    const int lr  = tid >> 2;        // 0..63
    const int blk = tid & 3;         // 16B block within 32-elem row chunk

    float acc[4][4][4];
#pragma unroll
    for (int mt = 0; mt < 4; mt++)
#pragma unroll
        for (int nt = 0; nt < 4; nt++)
#pragma unroll
            for (int e = 0; e < 4; e++) acc[mt][nt][e] = 0.f;

    // ldmatrix source addresses (byte offsets inside a stage)
    uint32_t aRow[4], bRow[2];
#pragma unroll
    for (int mt = 0; mt < 4; mt++)
        aRow[mt] = (uint32_t)(wm*64 + mt*16 + (lane & 15)) * 80;
    {
        int br = wn*32 + (lane & 7) + ((lane >> 4) & 1) * 8;
        bRow[0] = (uint32_t)br * 80;
        bRow[1] = (uint32_t)(br + 16) * 80;
    }
    const uint32_t aCB = (uint32_t)(lane >> 4) * 16;        // A col 16B-block
    const uint32_t bCB = (uint32_t)((lane >> 3) & 1) * 16;  // B col 16B-block

#define ISSUE(c) do {                                                          \
    uint32_t stb_ = sb + ((c) & 1) * ST_BYTES;                                 \
    int kofs_ = (c)*32 + blk*8;                                                \
    _Pragma("unroll")                                                          \
    for (int half = 0; half < 2; half++) {                                     \
        int r_ = lr + half*64;                                                 \
        uint32_t so_ = (uint32_t)r_*80 + (uint32_t)blk*16;                     \
        size_t go_ = (size_t)r_*DM + kofs_;                                    \
        cpa16(stb_ + OFF_AH + so_, Ah + go_);                                  \
        cpa16(stb_ + OFF_AL + so_, Al + go_);                                  \
        cpa16(stb_ + OFF_BH + so_, Bh + go_);                                  \
        cpa16(stb_ + OFF_BL + so_, Bl + go_);                                  \
    }                                                                          \
    asm volatile("cp.async.commit_group;" ::: "memory");                       \
} while (0)

    ISSUE(0);
    ISSUE(1);

    for (int c = 0; c < 32; c++) {
        if (c < 31) asm volatile("cp.async.wait_group 1;" ::: "memory");
        else        asm volatile("cp.async.wait_group 0;" ::: "memory");
        __syncthreads();

        uint32_t stb = sb + (c & 1) * ST_BYTES;
#pragma unroll
        for (int s = 0; s < 2; s++) {
            uint32_t ah[4][4], al[4][4], bh[2][4], bl[2][4];
            uint32_t aC = stb + (uint32_t)s*32 + aCB;
            uint32_t bC = stb + (uint32_t)s*32 + bCB;
#pragma unroll
            for (int mt = 0; mt < 4; mt++) {
                ldsm4(ah[mt], aC + OFF_AH + aRow[mt]);
                ldsm4(al[mt], aC + OFF_AL + aRow[mt]);
            }
#pragma unroll
            for (int p = 0; p < 2; p++) {
                ldsm4(bh[p], bC + OFF_BH + bRow[p]);
                ldsm4(bl[p], bC + OFF_BL + bRow[p]);
            }
#pragma unroll
            for (int mt = 0; mt < 4; mt++)
#pragma unroll
                for (int nt = 0; nt < 4; nt++) {
                    const uint32_t* bth = bh[nt >> 1] + (nt & 1) * 2;
                    const uint32_t* btl = bl[nt >> 1] + (nt & 1) * 2;
                    mma16816(acc[mt][nt], ah[mt], bth[0], bth[1]);
                    mma16816(acc[mt][nt], ah[mt], btl[0], btl[1]);
                    mma16816(acc[mt][nt], al[mt], bth[0], bth[1]);
                }
        }
        __syncthreads();
        if (c + 2 < 32) ISSUE(c + 2);
    }

    // ---- epilogue: stage C tile through smem (reuse pipeline buffers)
    float (*Cs)[136] = (float (*)[136])sm;
#pragma unroll
    for (int mt = 0; mt < 4; mt++)
#pragma unroll
        for (int nt = 0; nt < 4; nt++) {
            int row = wm*64 + mt*16 + (lane >> 2);
            int col = wn*32 + nt*8 + 2*(lane & 3);
            Cs[row    ][col] = acc[mt][nt][0]; Cs[row    ][col+1] = acc[mt][nt][1];
            Cs[row + 8][col] = acc[mt][nt][2]; Cs[row + 8][col+1] = acc[mt][nt][3];
        }
    __syncthreads();

    int b = by >> 4;                       // 128-row tile never crosses batch
    if (cmode >= 2) {
        int mr   = tid >> 1;               // 0..127
        int half = tid & 1;                // n half (64 cols)
        const float* src = &Cs[mr][half*64];
        if (cmode == 3) {
            float* dst = Cext + (size_t)(by*128 + mr)*DM + bx*128 + half*64;
#pragma unroll
            for (int j = 0; j < 16; j++)
                ((float4*)dst)[j] = ((const float4*)src)[j];
        } else {
            int h = (bx*128 + half*64) >> 6;
            int s = (by*128 + mr) & 2047;
            float* dst = g_v + ((size_t)(b*NH + h)*SEQ + s)*DH;
#pragma unroll
            for (int j = 0; j < 16; j++)
                ((float4*)dst)[j] = ((const float4*)src)[j];
        }
    } else {
        float* G = cmode ? g_kt : g_qt;
        int d_idx = tid >> 5;              // 0..7
        int s4    = (tid & 31) * 4;        // 4 consecutive s
        int sg    = (by*128 + s4) & 2047;
#pragma unroll
        for (int dd = 0; dd < 16; dd++) {
            int d = dd*8 + d_idx;          // 0..127 within tile
            int n = bx*128 + d;
            int h = n >> 6, dglob = n & 63;
            float4 v = make_float4(Cs[s4][d], Cs[s4+1][d], Cs[s4+2][d], Cs[s4+3][d]);
            *(float4*)(G + ((size_t)(b*NH + h)*DH + dglob)*SEQ + sg) = v;
        }
    }
#undef ISSUE
}

// ---------------- flash attention (fp32, online softmax, f32x2) -------------
__global__ __launch_bounds__(128) void attn_kernel() {
    __shared__ __align__(16) float qs [DH*64];
    __shared__ __align__(16) float kps[DH*64];
    __shared__ __align__(16) float vs [64*DH];

    int bh = blockIdx.y;
    int h  = bh & (NH-1);
    int b  = bh >> 4;
    int q0 = blockIdx.x * 64;
    int tid = threadIdx.x;
    int tx = tid & 15, ty = tid >> 4;

    const float* qg = g_qt + (size_t)bh * DH * SEQ;
    const float* kg = g_kt + (size_t)bh * DH * SEQ;
    const float* vg = g_v  + (size_t)bh * SEQ * DH;
    const float* biasrow = g_bias + h*4096;

    for (int e = tid; e < DH*16; e += 128) {
        int d = e >> 4, s4 = e & 15;
        ((float4*)qs)[d*16 + s4] = ((const float4*)(qg + (size_t)d*SEQ + q0))[s4];
    }

    u64 accP2[8][2];
    float mrow[8], lrow[8];
#pragma unroll
    for (int i = 0; i < 8; i++) {
        mrow[i] = -1e30f; lrow[i] = 0.f;
        accP2[i][0] = 0ull; accP2[i][1] = 0ull;
    }
    __syncthreads();

    for (int k0 = 0; k0 < SEQ; k0 += 64) {
        for (int e = tid; e < DH*16; e += 128) {
            int d = e >> 4, s4 = e & 15;
            ((float4*)kps)[e] = ((const float4*)(kg + (size_t)d*SEQ + k0))[s4];
            ((float4*)vs )[e] = ((const float4*)(vg + (size_t)k0*DH))[e];
        }
        __syncthreads();

        u64 sc2[4][4];
#pragma unroll
        for (int ip = 0; ip < 4; ip++)
#pragma unroll
            for (int j = 0; j < 4; j++) sc2[ip][j] = 0ull;

#pragma unroll 4
        for (int d = 0; d < DH; d++) {
            const float* qp = qs + d*64 + 8*ty;
            ulonglong2 qa = *(const ulonglong2*)qp;
            ulonglong2 qb = *(const ulonglong2*)(qp + 4);
            u64 ap[4] = {qa.x, qa.y, qb.x, qb.y};
            float4 kf = ((const float4*)kps)[d*16 + tx];
            u64 kd[4] = {pk2(kf.x,kf.x), pk2(kf.y,kf.y), pk2(kf.z,kf.z), pk2(kf.w,kf.w)};
#pragma unroll
            for (int ip = 0; ip < 4; ip++)
#pragma unroll
                for (int j = 0; j < 4; j++) fma2(sc2[ip][j], ap[ip], kd[j]);
        }

        float sc[8][4];
#pragma unroll
        for (int ip = 0; ip < 4; ip++)
#pragma unroll
            for (int j = 0; j < 4; j++) {
                sc[2*ip  ][j] = lo2(sc2[ip][j]);
                sc[2*ip+1][j] = hi2(sc2[ip][j]);
            }

        int relbase = k0 + 4*tx - (q0 + 8*ty) + 2047;
        float bvals[11];
#pragma unroll
        for (int t = 0; t < 11; t++) bvals[t] = biasrow[relbase - 7 + t];
#pragma unroll
        for (int i = 0; i < 8; i++)
#pragma unroll
            for (int j = 0; j < 4; j++) sc[i][j] += bvals[j - i + 7];

        __syncthreads();

#pragma unroll
        for (int i = 0; i < 8; i++) {
            float tm = fmaxf(fmaxf(sc[i][0], sc[i][1]), fmaxf(sc[i][2], sc[i][3]));
#pragma unroll
            for (int o = 8; o >= 1; o >>= 1)
                tm = fmaxf(tm, __shfl_xor_sync(0xffffffffu, tm, o));
            float mnew = fmaxf(mrow[i], tm);
            float corr = __expf(mrow[i] - mnew);
            mrow[i] = mnew;
            float p0 = __expf(sc[i][0] - mnew);
            float p1 = __expf(sc[i][1] - mnew);
            float p2 = __expf(sc[i][2] - mnew);
            float p3 = __expf(sc[i][3] - mnew);
            float psum = p0 + p1 + p2 + p3;
#pragma unroll
            for (int o = 8; o >= 1; o >>= 1)
                psum += __shfl_xor_sync(0xffffffffu, psum, o);
            lrow[i] = lrow[i]*corr + psum;
            u64 cd = pk2(corr, corr);
            mul2(accP2[i][0], cd);
            mul2(accP2[i][1], cd);
            ((float4*)kps)[(8*ty + i)*16 + (tx ^ ty)] = make_float4(p0, p1, p2, p3);
        }
        __syncthreads();

#pragma unroll 2
        for (int jj = 0; jj < 16; jj++) {
            int j0 = jj*4;
            ulonglong2 v0 = ((const ulonglong2*)vs)[(j0+0)*16 + tx];
            ulonglong2 v1 = ((const ulonglong2*)vs)[(j0+1)*16 + tx];
            ulonglong2 v2 = ((const ulonglong2*)vs)[(j0+2)*16 + tx];
            ulonglong2 v3 = ((const ulonglong2*)vs)[(j0+3)*16 + tx];
#pragma unroll
            for (int i = 0; i < 8; i++) {
                float4 pf = ((const float4*)kps)[(8*ty + i)*16 + (jj ^ ty)];
                u64 pd0 = pk2(pf.x, pf.x), pd1 = pk2(pf.y, pf.y);
                u64 pd2 = pk2(pf.z, pf.z), pd3 = pk2(pf.w, pf.w);
                fma2(accP2[i][0], pd0, v0.x); fma2(accP2[i][1], pd0, v0.y);
                fma2(accP2[i][0], pd1, v1.x); fma2(accP2[i][1], pd1, v1.y);
                fma2(accP2[i][0], pd2, v2.x); fma2(accP2[i][1], pd2, v2.y);
                fma2(accP2[i][0], pd3, v3.x); fma2(accP2[i][1], pd3, v3.y);
            }
        }
        __syncthreads();
    }

#pragma unroll
    for (int i = 0; i < 8; i++) {
        float inv = 1.0f / lrow[i];
        int m = q0 + 8*ty + i;
        float4 o4 = make_float4(lo2(accP2[i][0])*inv, hi2(accP2[i][0])*inv,
                                lo2(accP2[i][1])*inv, hi2(accP2[i][1])*inv);
        ((float4*)(g_o + ((size_t)b*SEQ + m)*DM + h*DH))[tx] = o4;
    }
}

// ---------------- launch -----------------------------------------------------
extern "C" void kernel_launch(void* const* d_in, const int* in_sizes, int n_in,
                              void* d_out, int out_size) {
    const float* X   = (const float*)d_in[0];
    const float* Wq  = (const float*)d_in[1];
    const float* Wk  = (const float*)d_in[2];
    const float* Wv  = (const float*)d_in[3];
    const float* Wo  = (const float*)d_in[4];
    const float* rel = (const float*)d_in[5];
    float* out = (float*)d_out;

    cudaFuncSetAttribute(gemm_mma, cudaFuncAttributeMaxDynamicSharedMemorySize, G_SMEM);

    bias_kernel<<<16, 256>>>(rel);
    conv_split<<<4096, 256>>>((const float4*)X, 0);
    conv_wT<<<dim3(32, 32, 4), dim3(32, 8)>>>(Wq, Wk, Wv, Wo);

    dim3 gg(8, 32);   // N tiles x M tiles
    gemm_mma<<<gg, 256, G_SMEM>>>(0, 0, nullptr, 0);   // Q
    gemm_mma<<<gg, 256, G_SMEM>>>(0, 1, nullptr, 1);   // K
    gemm_mma<<<gg, 256, G_SMEM>>>(0, 2, nullptr, 2);   // V

    attn_kernel<<<dim3(SEQ/64, BATCH*NH), 128>>>();

    conv_split<<<4096, 256>>>(nullptr, 1);
    gemm_mma<<<gg, 256, G_SMEM>>>(1, 3, out, 3);       // O projection
}

// round 6
// speedup vs baseline: 2.7995x; 1.7718x over previous
#include <cuda_runtime.h>
#include <cuda_bf16.h>
#include <math.h>
#include <stdint.h>

#define NH   16
#define DH   64
#define SEQ  2048
#define BATCH 2
#define DM   1024
#define MROWS (BATCH*SEQ)   // 4096

__device__ __forceinline__ uint32_t smem_u32(const void* p) {
    uint32_t a;
    asm("{ .reg .u64 t; cvta.to.shared.u64 t, %1; cvt.u32.u64 %0, t; }"
        : "=r"(a) : "l"(p));
    return a;
}
__device__ __forceinline__ void cpa16(uint32_t s, const void* g) {
    asm volatile("cp.async.cg.shared.global [%0], [%1], 16;" :: "r"(s), "l"(g));
}
__device__ __forceinline__ void ldsm4(uint32_t r[4], uint32_t a) {
    asm volatile("ldmatrix.sync.aligned.m8n8.x4.shared.b16 {%0,%1,%2,%3}, [%4];"
                 : "=r"(r[0]), "=r"(r[1]), "=r"(r[2]), "=r"(r[3]) : "r"(a));
}
__device__ __forceinline__ void mma16816(float c[4], const uint32_t a[4],
                                         const uint32_t b0, const uint32_t b1) {
    asm volatile("mma.sync.aligned.m16n8k16.row.col.f32.bf16.bf16.f32 "
        "{%0,%1,%2,%3}, {%4,%5,%6,%7}, {%8,%9}, {%0,%1,%2,%3};"
        : "+f"(c[0]), "+f"(c[1]), "+f"(c[2]), "+f"(c[3])
        : "r"(a[0]), "r"(a[1]), "r"(a[2]), "r"(a[3]), "r"(b0), "r"(b1));
}
// pack (x,y) -> bf16x2 (low = x); hi/lo exact split
__device__ __forceinline__ uint32_t cvt2(float x, float y) {
    uint32_t r; asm("cvt.rn.bf16x2.f32 %0, %1, %2;" : "=r"(r) : "f"(y), "f"(x));
    return r;
}
__device__ __forceinline__ void bsplit(uint32_t &hi, uint32_t &lo, float x, float y) {
    uint32_t h = cvt2(x, y);
    float xr = x - __uint_as_float(h << 16);
    float yr = y - __uint_as_float(h & 0xffff0000u);
    hi = h; lo = cvt2(xr, yr);
}

// ---------------- scratch (device globals; no allocations allowed) ----------
__device__ float g_bias[NH*4096];                      // [h][rel+2047]
__device__ __nv_bfloat16 g_xh[(size_t)MROWS*DM];       // X hi
__device__ __nv_bfloat16 g_xl[(size_t)MROWS*DM];       // X lo
__device__ __nv_bfloat16 g_oh[(size_t)MROWS*DM];       // attn-out hi
__device__ __nv_bfloat16 g_ol[(size_t)MROWS*DM];       // attn-out lo
__device__ __nv_bfloat16 g_wth[4*(size_t)DM*DM];       // W^T hi [w][n][k]
__device__ __nv_bfloat16 g_wtl[4*(size_t)DM*DM];       // W^T lo
__device__ __nv_bfloat16 g_qh[(size_t)BATCH*NH*SEQ*DH];  // Q hi [b,h,s,d]
__device__ __nv_bfloat16 g_ql[(size_t)BATCH*NH*SEQ*DH];
__device__ __nv_bfloat16 g_kh[(size_t)BATCH*NH*SEQ*DH];  // K hi [b,h,s,d]
__device__ __nv_bfloat16 g_kl[(size_t)BATCH*NH*SEQ*DH];
__device__ __nv_bfloat16 g_vh[(size_t)BATCH*NH*DH*SEQ];  // V hi [b,h,d,s]
__device__ __nv_bfloat16 g_vl[(size_t)BATCH*NH*DH*SEQ];

// ---------------- relative-position bias table ------------------------------
__global__ void bias_kernel(const float* __restrict__ rel_emb) {
    int idx = blockIdx.x * blockDim.x + threadIdx.x;   // 0..4094
    if (idx >= 4095) return;
    int rel = idx - 2047;
    int bucket = (rel > 0) ? 16 : 0;
    int r = abs(rel);
    int bval;
    if (r < 8) bval = r;
    else {
        float v = logf((float)r / 8.0f) / 2.772588722239781f * 8.0f;
        bval = min(8 + (int)v, 15);
    }
    bucket += bval;
#pragma unroll
    for (int h = 0; h < NH; h++)
        g_bias[h*4096 + idx] = rel_emb[bucket*NH + h];
}

// ---------------- fp32 -> bf16 hi/lo split of X -----------------------------
__global__ void conv_split(const float4* __restrict__ src) {
    int i = blockIdx.x * blockDim.x + threadIdx.x;    // 1048576
    float4 v = src[i];
    uint32_t h0, l0, h1, l1;
    bsplit(h0, l0, v.x, v.y);
    bsplit(h1, l1, v.z, v.w);
    ((uint32_t*)g_xh)[2*i] = h0; ((uint32_t*)g_xh)[2*i+1] = h1;
    ((uint32_t*)g_xl)[2*i] = l0; ((uint32_t*)g_xl)[2*i+1] = l1;
}

// ---------------- weight transpose + split: W[K][N] -> W^T[N][K] bf16 -------
__global__ void conv_wT(const float* __restrict__ W0, const float* __restrict__ W1,
                        const float* __restrict__ W2, const float* __restrict__ W3) {
    __shared__ float t[32][33];
    int z = blockIdx.z;
    const float* W = (z == 0) ? W0 : (z == 1) ? W1 : (z == 2) ? W2 : W3;
    __nv_bfloat16* oh = g_wth + (size_t)z*DM*DM;
    __nv_bfloat16* ol = g_wtl + (size_t)z*DM*DM;
    int k0 = blockIdx.y*32, n0 = blockIdx.x*32;
    int tx = threadIdx.x, ty = threadIdx.y;   // (32, 8)
#pragma unroll
    for (int j = 0; j < 4; j++)
        t[tx][ty + 8*j] = W[(size_t)(k0 + ty + 8*j)*DM + n0 + tx];
    __syncthreads();
#pragma unroll
    for (int j = 0; j < 4; j++) {
        float v = t[ty + 8*j][tx];
        __nv_bfloat16 h = __float2bfloat16(v);
        __nv_bfloat16 l = __float2bfloat16(v - __bfloat162float(h));
        size_t o = (size_t)(n0 + ty + 8*j)*DM + k0 + tx;
        oh[o] = h; ol[o] = l;
    }
}

// ---------------- warp-MMA GEMM (HMMA bf16, 3-pass hi/lo) -------------------
// C[4096,1024] = A @ W.  CTA tile 128x128, 8 warps of 64x32, K chunk 32.
// cmode: 0 -> Q hi/lo [b,h,s,d], 1 -> K hi/lo, 2 -> V hi/lo [b,h,d,s],
//        3 -> Cext fp32 row-major
#define ST_BYTES 40960
#define OFF_AH 0
#define OFF_AL 10240
#define OFF_BH 20480
#define OFF_BL 30720
#define G_SMEM (2*ST_BYTES)     // 81920; also >= 128*136*4 epilogue floats

__global__ __launch_bounds__(256) void gemm_mma(int asel, int wsel,
                                                float* __restrict__ Cext, int cmode) {
    extern __shared__ __align__(16) char sm[];
    uint32_t sb = smem_u32(sm);
    const int tid = threadIdx.x, lane = tid & 31, w = tid >> 5;
    const int wm = w >> 2, wn = w & 3;
    const int bx = blockIdx.x, by = blockIdx.y;

    const __nv_bfloat16* Ah = (asel ? g_oh : g_xh) + (size_t)(by*128)*DM;
    const __nv_bfloat16* Al = (asel ? g_ol : g_xl) + (size_t)(by*128)*DM;
    const __nv_bfloat16* Bh = g_wth + (size_t)wsel*DM*DM + (size_t)(bx*128)*DM;
    const __nv_bfloat16* Bl = g_wtl + (size_t)wsel*DM*DM + (size_t)(bx*128)*DM;

    const int lr  = tid >> 2;
    const int blk = tid & 3;

    float acc[4][4][4];
#pragma unroll
    for (int mt = 0; mt < 4; mt++)
#pragma unroll
        for (int nt = 0; nt < 4; nt++)
#pragma unroll
            for (int e = 0; e < 4; e++) acc[mt][nt][e] = 0.f;

    uint32_t aRow[4], bRow[2];
#pragma unroll
    for (int mt = 0; mt < 4; mt++)
        aRow[mt] = (uint32_t)(wm*64 + mt*16 + (lane & 15)) * 80;
    {
        int br = wn*32 + (lane & 7) + ((lane >> 4) & 1) * 8;
        bRow[0] = (uint32_t)br * 80;
        bRow[1] = (uint32_t)(br + 16) * 80;
    }
    const uint32_t aCB = (uint32_t)(lane >> 4) * 16;
    const uint32_t bCB = (uint32_t)((lane >> 3) & 1) * 16;

#define ISSUE(c) do {                                                          \
    uint32_t stb_ = sb + ((c) & 1) * ST_BYTES;                                 \
    int kofs_ = (c)*32 + blk*8;                                                \
    _Pragma("unroll")                                                          \
    for (int half = 0; half < 2; half++) {                                     \
        int r_ = lr + half*64;                                                 \
        uint32_t so_ = (uint32_t)r_*80 + (uint32_t)blk*16;                     \
        size_t go_ = (size_t)r_*DM + kofs_;                                    \
        cpa16(stb_ + OFF_AH + so_, Ah + go_);                                  \
        cpa16(stb_ + OFF_AL + so_, Al + go_);                                  \
        cpa16(stb_ + OFF_BH + so_, Bh + go_);                                  \
        cpa16(stb_ + OFF_BL + so_, Bl + go_);                                  \
    }                                                                          \
    asm volatile("cp.async.commit_group;" ::: "memory");                       \
} while (0)

    ISSUE(0);
    ISSUE(1);

    for (int c = 0; c < 32; c++) {
        if (c < 31) asm volatile("cp.async.wait_group 1;" ::: "memory");
        else        asm volatile("cp.async.wait_group 0;" ::: "memory");
        __syncthreads();

        uint32_t stb = sb + (c & 1) * ST_BYTES;
#pragma unroll
        for (int s = 0; s < 2; s++) {
            uint32_t ah[4][4], al[4][4], bh[2][4], bl[2][4];
            uint32_t aC = stb + (uint32_t)s*32 + aCB;
            uint32_t bC = stb + (uint32_t)s*32 + bCB;
#pragma unroll
            for (int mt = 0; mt < 4; mt++) {
                ldsm4(ah[mt], aC + OFF_AH + aRow[mt]);
                ldsm4(al[mt], aC + OFF_AL + aRow[mt]);
            }
#pragma unroll
            for (int p = 0; p < 2; p++) {
                ldsm4(bh[p], bC + OFF_BH + bRow[p]);
                ldsm4(bl[p], bC + OFF_BL + bRow[p]);
            }
#pragma unroll
            for (int mt = 0; mt < 4; mt++)
#pragma unroll
                for (int nt = 0; nt < 4; nt++) {
                    const uint32_t* bth = bh[nt >> 1] + (nt & 1) * 2;
                    const uint32_t* btl = bl[nt >> 1] + (nt & 1) * 2;
                    mma16816(acc[mt][nt], ah[mt], bth[0], bth[1]);
                    mma16816(acc[mt][nt], ah[mt], btl[0], btl[1]);
                    mma16816(acc[mt][nt], al[mt], bth[0], bth[1]);
                }
        }
        __syncthreads();
        if (c + 2 < 32) ISSUE(c + 2);
    }

    // ---- epilogue: stage C tile through smem (reuse pipeline buffers)
    float (*Cs)[136] = (float (*)[136])sm;
#pragma unroll
    for (int mt = 0; mt < 4; mt++)
#pragma unroll
        for (int nt = 0; nt < 4; nt++) {
            int row = wm*64 + mt*16 + (lane >> 2);
            int col = wn*32 + nt*8 + 2*(lane & 3);
            Cs[row    ][col] = acc[mt][nt][0]; Cs[row    ][col+1] = acc[mt][nt][1];
            Cs[row + 8][col] = acc[mt][nt][2]; Cs[row + 8][col+1] = acc[mt][nt][3];
        }
    __syncthreads();

    int b = by >> 4;
    if (cmode == 3) {
        int mr = tid >> 1, half = tid & 1;
        const float* src = &Cs[mr][half*64];
        float* dst = Cext + (size_t)(by*128 + mr)*DM + bx*128 + half*64;
#pragma unroll
        for (int j = 0; j < 16; j++)
            ((float4*)dst)[j] = ((const float4*)src)[j];
    } else if (cmode <= 1) {
        // Q/K hi/lo: [b,h,s,d], d contiguous
        int mr = tid >> 1, half = tid & 1;
        int hh = bx*2 + half;
        int s  = (by & 15)*128 + mr;
        __nv_bfloat16* DST_H = cmode ? g_kh : g_qh;
        __nv_bfloat16* DST_L = cmode ? g_kl : g_ql;
        size_t base = ((size_t)(b*NH + hh)*SEQ + s)*DH;
        const float* src = &Cs[mr][half*64];
#pragma unroll
        for (int j8 = 0; j8 < 8; j8++) {
            uint32_t hv[4], lv[4];
#pragma unroll
            for (int e = 0; e < 4; e++)
                bsplit(hv[e], lv[e], src[j8*8 + 2*e], src[j8*8 + 2*e + 1]);
            *(uint4*)(DST_H + base + j8*8) = make_uint4(hv[0], hv[1], hv[2], hv[3]);
            *(uint4*)(DST_L + base + j8*8) = make_uint4(lv[0], lv[1], lv[2], lv[3]);
        }
    } else {
        // V hi/lo: [b,h,d,s], s contiguous
        int d_idx = tid >> 5;
        int s4    = (tid & 31) * 4;
        int sg    = (by & 15)*128 + s4;
#pragma unroll
        for (int dd = 0; dd < 16; dd++) {
            int d = dd*8 + d_idx;
            int n = bx*128 + d;
            int hh = n >> 6, dg = n & 63;
            uint32_t h0, l0, h1, l1;
            bsplit(h0, l0, Cs[s4][d],   Cs[s4+1][d]);
            bsplit(h1, l1, Cs[s4+2][d], Cs[s4+3][d]);
            size_t base = ((size_t)(b*NH + hh)*DH + dg)*SEQ + sg;
            *(uint2*)(g_vh + base) = make_uint2(h0, h1);
            *(uint2*)(g_vl + base) = make_uint2(l0, l1);
        }
    }
#undef ISSUE
}

// ---------------- flash attention, HMMA bf16 3-pass -------------------------
// grid (SEQ/64, B*H), 128 threads (4 warps, each warp m16).
// smem: 2 stages x {Kh,Kl,Vh,Vl} 8KB each = 64KB.
#define AT_STG 32768
__global__ __launch_bounds__(128, 3) void attn_mma() {
    extern __shared__ __align__(16) char asmem[];
    uint32_t sb = smem_u32(asmem);
    const int tid = threadIdx.x, lane = tid & 31, w = tid >> 5;
    const int bh = blockIdx.y, h = bh & (NH-1), b = bh >> 4;
    const int q0 = blockIdx.x * 64;
    const int lr8 = lane & 7, lg = lane >> 3;   // ldmatrix group
    const int r0 = w*16 + (lane >> 2);          // local q row (and +8)
    const int qc = 2*(lane & 3);                // col pair base

    const __nv_bfloat16* Qh_g = g_qh + ((size_t)bh*SEQ + q0)*DH;
    const __nv_bfloat16* Ql_g = g_ql + ((size_t)bh*SEQ + q0)*DH;
    const __nv_bfloat16* Kh_g = g_kh + (size_t)bh*SEQ*DH;
    const __nv_bfloat16* Kl_g = g_kl + (size_t)bh*SEQ*DH;
    const __nv_bfloat16* Vh_g = g_vh + (size_t)bh*DH*SEQ;
    const __nv_bfloat16* Vl_g = g_vl + (size_t)bh*DH*SEQ;
    const float* biasrow = g_bias + h*4096;

    // Q fragments (direct LDG, 4 k-tiles, hi+lo)
    uint32_t aqh[4][4], aql[4][4];
#pragma unroll
    for (int kt = 0; kt < 4; kt++) {
        int c0 = kt*16 + qc;
        aqh[kt][0] = *(const uint32_t*)(Qh_g + (size_t)r0*DH + c0);
        aqh[kt][1] = *(const uint32_t*)(Qh_g + (size_t)(r0+8)*DH + c0);
        aqh[kt][2] = *(const uint32_t*)(Qh_g + (size_t)r0*DH + c0 + 8);
        aqh[kt][3] = *(const uint32_t*)(Qh_g + (size_t)(r0+8)*DH + c0 + 8);
        aql[kt][0] = *(const uint32_t*)(Ql_g + (size_t)r0*DH + c0);
        aql[kt][1] = *(const uint32_t*)(Ql_g + (size_t)(r0+8)*DH + c0);
        aql[kt][2] = *(const uint32_t*)(Ql_g + (size_t)r0*DH + c0 + 8);
        aql[kt][3] = *(const uint32_t*)(Ql_g + (size_t)(r0+8)*DH + c0 + 8);
    }

    float o[8][4];
#pragma unroll
    for (int nt = 0; nt < 8; nt++)
#pragma unroll
        for (int e = 0; e < 4; e++) o[nt][e] = 0.f;
    float m0 = -1e30f, m1 = -1e30f, l0 = 0.f, l1 = 0.f;

#define AISSUE(it_) do {                                                        \
    int k0_ = (it_)*64;                                                         \
    uint32_t stb_ = sb + ((it_) & 1)*AT_STG;                                    \
    _Pragma("unroll")                                                           \
    for (int i_ = 0; i_ < 16; i_++) {                                           \
        int id_ = tid + i_*128;                                                 \
        int arr_ = id_ >> 9, rem_ = id_ & 511, row_ = rem_ >> 3, bk_ = rem_ & 7;\
        uint32_t dst_ = stb_ + arr_*8192 + row_*128 + ((bk_ ^ (row_ & 7))*16);  \
        const __nv_bfloat16* src_;                                              \
        if (arr_ == 0)      src_ = Kh_g + (size_t)(k0_ + row_)*DH + bk_*8;      \
        else if (arr_ == 1) src_ = Kl_g + (size_t)(k0_ + row_)*DH + bk_*8;      \
        else if (arr_ == 2) src_ = Vh_g + (size_t)row_*SEQ + k0_ + bk_*8;       \
        else                src_ = Vl_g + (size_t)row_*SEQ + k0_ + bk_*8;       \
        cpa16(dst_, src_);                                                      \
    }                                                                           \
    asm volatile("cp.async.commit_group;" ::: "memory");                        \
} while (0)

    AISSUE(0);
    AISSUE(1);

    for (int it = 0; it < 32; it++) {
        if (it < 31) asm volatile("cp.async.wait_group 1;" ::: "memory");
        else         asm volatile("cp.async.wait_group 0;" ::: "memory");
        __syncthreads();
        uint32_t stg = sb + (it & 1)*AT_STG;

        // ---- S = Q K^T + bias (3-pass)
        float sc[8][4];
#pragma unroll
        for (int nt = 0; nt < 8; nt++)
#pragma unroll
            for (int e = 0; e < 4; e++) sc[nt][e] = 0.f;

#pragma unroll
        for (int kt = 0; kt < 4; kt++)
#pragma unroll
            for (int nb = 0; nb < 4; nb++) {
                int row = nb*16 + lr8 + (lg >> 1)*8;
                int bk  = 2*kt + (lg & 1);
                uint32_t ad = stg + row*128 + ((bk ^ (row & 7))*16);
                uint32_t kh[4], kl[4];
                ldsm4(kh, ad);
                ldsm4(kl, ad + 8192);
                mma16816(sc[2*nb],   aqh[kt], kh[0], kh[1]);
                mma16816(sc[2*nb+1], aqh[kt], kh[2], kh[3]);
                mma16816(sc[2*nb],   aqh[kt], kl[0], kl[1]);
                mma16816(sc[2*nb+1], aqh[kt], kl[2], kl[3]);
                mma16816(sc[2*nb],   aql[kt], kh[0], kh[1]);
                mma16816(sc[2*nb+1], aql[kt], kh[2], kh[3]);
            }

        // bias
        {
            int relb = it*64 + qc - (q0 + r0) + 2047;
            float bb0[9], bb1[9];
#pragma unroll
            for (int t = 0; t < 9; t++) {
                bb0[t] = biasrow[relb - 8 + t*8];
                bb1[t] = biasrow[relb - 7 + t*8];
            }
#pragma unroll
            for (int nt = 0; nt < 8; nt++) {
                sc[nt][0] += bb0[nt+1]; sc[nt][1] += bb1[nt+1];
                sc[nt][2] += bb0[nt];   sc[nt][3] += bb1[nt];
            }
        }

        // ---- online softmax (rows r0 and r0+8, quad reduction)
        float mx0 = sc[0][0], mx1 = sc[0][2];
#pragma unroll
        for (int nt = 0; nt < 8; nt++) {
            mx0 = fmaxf(mx0, fmaxf(sc[nt][0], sc[nt][1]));
            mx1 = fmaxf(mx1, fmaxf(sc[nt][2], sc[nt][3]));
        }
        mx0 = fmaxf(mx0, __shfl_xor_sync(0xffffffffu, mx0, 1));
        mx0 = fmaxf(mx0, __shfl_xor_sync(0xffffffffu, mx0, 2));
        mx1 = fmaxf(mx1, __shfl_xor_sync(0xffffffffu, mx1, 1));
        mx1 = fmaxf(mx1, __shfl_xor_sync(0xffffffffu, mx1, 2));
        float m0n = fmaxf(m0, mx0), m1n = fmaxf(m1, mx1);
        float c0 = __expf(m0 - m0n), c1 = __expf(m1 - m1n);
        m0 = m0n; m1 = m1n;
        float s0 = 0.f, s1 = 0.f;
#pragma unroll
        for (int nt = 0; nt < 8; nt++) {
            sc[nt][0] = __expf(sc[nt][0] - m0n);
            sc[nt][1] = __expf(sc[nt][1] - m0n);
            sc[nt][2] = __expf(sc[nt][2] - m1n);
            sc[nt][3] = __expf(sc[nt][3] - m1n);
            s0 += sc[nt][0] + sc[nt][1];
            s1 += sc[nt][2] + sc[nt][3];
        }
        s0 += __shfl_xor_sync(0xffffffffu, s0, 1);
        s0 += __shfl_xor_sync(0xffffffffu, s0, 2);
        s1 += __shfl_xor_sync(0xffffffffu, s1, 1);
        s1 += __shfl_xor_sync(0xffffffffu, s1, 2);
        l0 = l0*c0 + s0; l1 = l1*c1 + s1;
#pragma unroll
        for (int nt = 0; nt < 8; nt++) {
            o[nt][0] *= c0; o[nt][1] *= c0;
            o[nt][2] *= c1; o[nt][3] *= c1;
        }

        // ---- O += P V (3-pass; P split hi/lo on the fly)
#pragma unroll
        for (int kt = 0; kt < 4; kt++) {
            uint32_t ph[4], pl[4];
            bsplit(ph[0], pl[0], sc[2*kt][0],   sc[2*kt][1]);
            bsplit(ph[1], pl[1], sc[2*kt][2],   sc[2*kt][3]);
            bsplit(ph[2], pl[2], sc[2*kt+1][0], sc[2*kt+1][1]);
            bsplit(ph[3], pl[3], sc[2*kt+1][2], sc[2*kt+1][3]);
#pragma unroll
            for (int nb = 0; nb < 4; nb++) {
                int row = nb*16 + lr8 + (lg >> 1)*8;
                int bk  = 2*kt + (lg & 1);
                uint32_t ad = stg + 16384 + row*128 + ((bk ^ (row & 7))*16);
                uint32_t vh[4], vl[4];
                ldsm4(vh, ad);
                ldsm4(vl, ad + 8192);
                mma16816(o[2*nb],   ph, vh[0], vh[1]);
                mma16816(o[2*nb+1], ph, vh[2], vh[3]);
                mma16816(o[2*nb],   ph, vl[0], vl[1]);
                mma16816(o[2*nb+1], ph, vl[2], vl[3]);
                mma16816(o[2*nb],   pl, vh[0], vh[1]);
                mma16816(o[2*nb+1], pl, vh[2], vh[3]);
            }
        }
        __syncthreads();
        if (it + 2 < 32) AISSUE(it + 2);
    }

    // ---- normalize, split, store to g_oh/g_ol  [b,s,h*64+d]
    float inv0 = 1.0f / l0, inv1 = 1.0f / l1;
    size_t ro0 = ((size_t)b*SEQ + q0 + r0)*DM + h*DH + qc;
    size_t ro1 = ro0 + (size_t)8*DM;
#pragma unroll
    for (int nt = 0; nt < 8; nt++) {
        uint32_t hv, lv;
        bsplit(hv, lv, o[nt][0]*inv0, o[nt][1]*inv0);
        *(uint32_t*)(g_oh + ro0 + nt*8) = hv;
        *(uint32_t*)(g_ol + ro0 + nt*8) = lv;
        bsplit(hv, lv, o[nt][2]*inv1, o[nt][3]*inv1);
        *(uint32_t*)(g_oh + ro1 + nt*8) = hv;
        *(uint32_t*)(g_ol + ro1 + nt*8) = lv;
    }
#undef AISSUE
}

// ---------------- launch -----------------------------------------------------
extern "C" void kernel_launch(void* const* d_in, const int* in_sizes, int n_in,
                              void* d_out, int out_size) {
    const float* X   = (const float*)d_in[0];
    const float* Wq  = (const float*)d_in[1];
    const float* Wk  = (const float*)d_in[2];
    const float* Wv  = (const float*)d_in[3];
    const float* Wo  = (const float*)d_in[4];
    const float* rel = (const float*)d_in[5];
    float* out = (float*)d_out;

    cudaFuncSetAttribute(gemm_mma, cudaFuncAttributeMaxDynamicSharedMemorySize, G_SMEM);
    cudaFuncSetAttribute(attn_mma, cudaFuncAttributeMaxDynamicSharedMemorySize, 2*AT_STG);

    bias_kernel<<<16, 256>>>(rel);
    conv_split<<<4096, 256>>>((const float4*)X);
    conv_wT<<<dim3(32, 32, 4), dim3(32, 8)>>>(Wq, Wk, Wv, Wo);

    dim3 gg(8, 32);
    gemm_mma<<<gg, 256, G_SMEM>>>(0, 0, nullptr, 0);   // Q
    gemm_mma<<<gg, 256, G_SMEM>>>(0, 1, nullptr, 1);   // K
    gemm_mma<<<gg, 256, G_SMEM>>>(0, 2, nullptr, 2);   // V

    attn_mma<<<dim3(SEQ/64, BATCH*NH), 128, 2*AT_STG>>>();

    gemm_mma<<<gg, 256, G_SMEM>>>(1, 3, out, 3);       // O projection
}